// round 1
// baseline (speedup 1.0000x reference)
#include <cuda_runtime.h>

#define BATCH 4
#define NINST 16
#define M_TOT 64
#define HF 120
#define WF 160
#define C_IN 128
#define H_OUT 480
#define W_OUT 640
#define SZ_IMG (M_TOT * H_OUT * W_OUT)   // 19,660,800

// Scratch (zero-initialized at load; padded borders stay zero forever).
__device__ float g_roi[M_TOT * C_IN * 16 * 16];   // [m][c][y 0..15][x 0..15], interior at [1..14]
__device__ float g_h1 [M_TOT * 64   * 16 * 16];   // padded conv_c1 output
__device__ float g_gap[M_TOT * C_IN];
__device__ float g_c  [M_TOT * 196];
__device__ float g_ss [M_TOT * 2];

// ---------------------------------------------------------------------------
// K1: ROI align. grid 64 (one block per instance), 256 threads.
// ---------------------------------------------------------------------------
__global__ void k_roi(const float* __restrict__ fmap, const float* __restrict__ boxes)
{
    int m = blockIdx.x;
    int b = m >> 4;
    __shared__ int   y0s[14], x0s[14];
    __shared__ float wys[14], wxs[14];

    float b0 = boxes[m*4+0], b1 = boxes[m*4+1], b2 = boxes[m*4+2], b3 = boxes[m*4+3];
    float y1 = 0.6f*b0, x1 = 0.6f*b1;
    float y2 = y1 + 0.1f + 0.3f*b2;
    float x2 = x1 + 0.1f + 0.3f*b3;

    int tid = threadIdx.x;
    if (tid < 14) {
        float t  = (tid + 0.5f) / 14.0f;
        float ys = (y1 + (y2 - y1) * t) * (float)(HF - 1);
        int y0 = (int)floorf(ys);
        if (y0 < 0) y0 = 0; if (y0 > HF-2) y0 = HF-2;
        y0s[tid] = y0;
        wys[tid] = fminf(fmaxf(ys - (float)y0, 0.f), 1.f);
    } else if (tid >= 32 && tid < 46) {
        int j = tid - 32;
        float t  = (j + 0.5f) / 14.0f;
        float xs = (x1 + (x2 - x1) * t) * (float)(WF - 1);
        int x0 = (int)floorf(xs);
        if (x0 < 0) x0 = 0; if (x0 > WF-2) x0 = WF-2;
        x0s[j] = x0;
        wxs[j] = fminf(fmaxf(xs - (float)x0, 0.f), 1.f);
    }
    __syncthreads();

    for (int flat = tid; flat < C_IN * 196; flat += blockDim.x) {
        int c = flat / 196, r = flat % 196;
        int i = r / 14, j = r % 14;
        int y0 = y0s[i], x0 = x0s[j];
        float wy = wys[i], wx = wxs[j];
        const float* f = fmap + (((size_t)(b*C_IN + c) * HF + y0) * WF + x0);
        float v00 = f[0], v01 = f[1], v10 = f[WF], v11 = f[WF+1];
        float v = (1.f-wy)*((1.f-wx)*v00 + wx*v01) + wy*((1.f-wx)*v10 + wx*v11);
        g_roi[((m*C_IN + c)*16 + (i+1))*16 + (j+1)] = v;
    }
}

// ---------------------------------------------------------------------------
// K2: fused conv_s (+ReLU+GAP) and conv_c1 (+ReLU, padded store).
// grid (6, 64): blockIdx.x = 32-channel block (0..3 -> conv_s, 4..5 -> conv_c1),
// blockIdx.y = instance. 224 threads; 196 compute threads own 8co x 4pos tiles.
// ---------------------------------------------------------------------------
__global__ void k_conv(const float* __restrict__ w_s_all,  const float* __restrict__ b_s_all,
                       const float* __restrict__ w_c1_all, const float* __restrict__ b_c1_all,
                       const int* __restrict__ labels)
{
    int cb  = blockIdx.x;
    int m   = blockIdx.y;
    int lab = labels[m];
    bool is_s = (cb < 4);
    int co0 = is_s ? cb*32 : (cb-4)*32;
    const float* wg = is_s ? (w_s_all  + (size_t)lab*C_IN*C_IN*9 + (size_t)co0*C_IN*9)
                           : (w_c1_all + (size_t)lab*64*C_IN*9   + (size_t)co0*C_IN*9);
    const float* bg = is_s ? (b_s_all + lab*C_IN + co0) : (b_c1_all + lab*64 + co0);

    __shared__ float w_sh[32*144];   // [co_local][ci_local*9+k]
    __shared__ float in_sh[16*256];  // [ci_local][y16][x16]
    __shared__ float gap_sh[32];

    int tid = threadIdx.x;
    if (tid < 32) gap_sh[tid] = 0.f;

    int cg = 0, pg = 0;
    int off[4];
    if (tid < 196) {
        cg = tid / 49; pg = tid % 49;
        #pragma unroll
        for (int u = 0; u < 4; ++u) {
            int p = pg*4 + u;
            off[u] = (p/14)*16 + (p%14);
        }
    }

    float acc[8][4];
    #pragma unroll
    for (int o = 0; o < 8; ++o)
        #pragma unroll
        for (int u = 0; u < 4; ++u) acc[o][u] = 0.f;

    const float* roi_base = g_roi + (size_t)m * C_IN * 256;

    for (int chunk = 0; chunk < 8; ++chunk) {
        __syncthreads();
        for (int t = tid; t < 32*144; t += 224) {
            int co = t / 144, r = t % 144;
            w_sh[co*144 + r] = wg[(size_t)co*1152 + chunk*144 + r];
        }
        for (int t = tid; t < 16*256; t += 224)
            in_sh[t] = roi_base[chunk*16*256 + t];
        __syncthreads();

        if (tid < 196) {
            #pragma unroll 1
            for (int ci = 0; ci < 16; ++ci) {
                const float* wrow = &w_sh[cg*8*144 + ci*9];
                const float* irow = &in_sh[ci*256];
                #pragma unroll
                for (int k = 0; k < 9; ++k) {
                    const int d = (k/3)*16 + (k%3);
                    float iv[4];
                    #pragma unroll
                    for (int u = 0; u < 4; ++u) iv[u] = irow[off[u] + d];
                    #pragma unroll
                    for (int o = 0; o < 8; ++o) {
                        float wv = wrow[o*144 + k];
                        #pragma unroll
                        for (int u = 0; u < 4; ++u) acc[o][u] = fmaf(wv, iv[u], acc[o][u]);
                    }
                }
            }
        }
    }
    __syncthreads();

    if (tid < 196) {
        if (is_s) {
            #pragma unroll
            for (int o = 0; o < 8; ++o) {
                float bv = bg[cg*8 + o];
                float s = 0.f;
                #pragma unroll
                for (int u = 0; u < 4; ++u) s += fmaxf(acc[o][u] + bv, 0.f);
                atomicAdd(&gap_sh[cg*8 + o], s);
            }
        } else {
            #pragma unroll
            for (int o = 0; o < 8; ++o) {
                float bv = bg[cg*8 + o];
                int co = co0 + cg*8 + o;
                #pragma unroll
                for (int u = 0; u < 4; ++u) {
                    int i = off[u] >> 4, j = off[u] & 15;
                    g_h1[((m*64 + co)*16 + i + 1)*16 + (j + 1)] =
                        fmaxf(acc[o][u] + bv, 0.f);
                }
            }
        }
    }
    if (is_s) {
        __syncthreads();
        if (tid < 32)
            g_gap[m*C_IN + co0 + tid] = gap_sh[tid] * (1.0f/196.0f);
    }
}

// ---------------------------------------------------------------------------
// K3: FC head -> scale, shift. 1 block, 64 threads.
// ---------------------------------------------------------------------------
__global__ void k_fc(const float* __restrict__ w_fc, const float* __restrict__ b_fc,
                     const int* __restrict__ labels, float* __restrict__ out)
{
    int m = threadIdx.x;
    if (m >= M_TOT) return;
    int lab = labels[m];
    float s0 = b_fc[lab*2 + 0];
    float s1 = b_fc[lab*2 + 1];
    const float* w0 = w_fc + (size_t)(lab*2 + 0) * 128;
    const float* w1 = w_fc + (size_t)(lab*2 + 1) * 128;
    const float* g  = g_gap + m*128;
    for (int c = 0; c < 128; ++c) {
        float gv = g[c];
        s0 = fmaf(gv, w0[c], s0);
        s1 = fmaf(gv, w1[c], s1);
    }
    g_ss[m*2 + 0] = s0;
    g_ss[m*2 + 1] = s1;
    out[(size_t)2*SZ_IMG + m]      = s0;   // scale
    out[(size_t)2*SZ_IMG + 64 + m] = s1;   // shift
}

// ---------------------------------------------------------------------------
// K4: conv_c2 (64 -> 1). grid 64, 224 threads (196 compute).
// ---------------------------------------------------------------------------
__global__ void k_conv2(const float* __restrict__ w2_all, const float* __restrict__ b2_all,
                        const int* __restrict__ labels)
{
    int m = blockIdx.x;
    int lab = labels[m];
    __shared__ float w2[576];
    __shared__ float b2v;
    int tid = threadIdx.x;
    const float* wgp = w2_all + (size_t)lab * 576;
    for (int t = tid; t < 576; t += 224) w2[t] = wgp[t];
    if (tid == 0) b2v = b2_all[lab];
    __syncthreads();

    if (tid < 196) {
        int i = tid / 14, j = tid % 14;
        const float* h = g_h1 + (size_t)m * 64 * 256;
        float acc = 0.f;
        for (int ci = 0; ci < 64; ++ci) {
            const float* hh = h + ci*256 + i*16 + j;
            #pragma unroll
            for (int k = 0; k < 9; ++k)
                acc = fmaf(w2[ci*9 + k], hh[(k/3)*16 + (k%3)], acc);
        }
        g_c[m*196 + tid] = acc + b2v;
    }
}

// ---------------------------------------------------------------------------
// K5: bilinear upsample 14x14 -> 480x640 (half-pixel, clamped) + scale/shift.
// grid (480, 64): one row per block; 320 threads, 2 px each, float2 stores.
// ---------------------------------------------------------------------------
__global__ void k_resize(float* __restrict__ out)
{
    int Y = blockIdx.x;
    int m = blockIdx.y;
    __shared__ float r0[14], r1[14];
    __shared__ float s_sc, s_sh;
    int tid = threadIdx.x;

    float iy = (Y + 0.5f) * (14.0f/480.0f) - 0.5f;
    iy = fminf(fmaxf(iy, 0.f), 13.f);
    int y0 = (int)iy; if (y0 > 12) y0 = 12;
    float fy = iy - (float)y0;

    if (tid < 14) {
        r0[tid] = g_c[m*196 + y0*14 + tid];
        r1[tid] = g_c[m*196 + (y0+1)*14 + tid];
    }
    if (tid == 14) s_sc = g_ss[m*2 + 0];
    if (tid == 15) s_sh = g_ss[m*2 + 1];
    __syncthreads();

    float scale = s_sc, shift = s_sh;
    size_t base = (size_t)m * H_OUT * W_OUT + (size_t)Y * W_OUT;

    float can2[2], dep2[2];
    #pragma unroll
    for (int u = 0; u < 2; ++u) {
        int X = tid*2 + u;
        float ix = (X + 0.5f) * (14.0f/640.0f) - 0.5f;
        ix = fminf(fmaxf(ix, 0.f), 13.f);
        int x0 = (int)ix; if (x0 > 12) x0 = 12;
        float fx = ix - (float)x0;
        float top = (1.f-fx)*r0[x0] + fx*r0[x0+1];
        float bot = (1.f-fx)*r1[x0] + fx*r1[x0+1];
        float can = (1.f-fy)*top + fy*bot;
        can2[u] = can;
        dep2[u] = fmaxf(can*scale + shift, 0.001f);
    }
    ((float2*)(out + base))[tid]          = make_float2(dep2[0], dep2[1]);   // depth_r
    ((float2*)(out + SZ_IMG + base))[tid] = make_float2(can2[0], can2[1]);   // canonical
}

// ---------------------------------------------------------------------------
extern "C" void kernel_launch(void* const* d_in, const int* in_sizes, int n_in,
                              void* d_out, int out_size)
{
    (void)in_sizes; (void)out_size;
    // Front-anchored: depth, context, input_feature_map. End-anchored: last 10
    // tensors are boxes..b_conv_c2 (robust to how the 3 scalar args are passed).
    const float* fmap      = (const float*)d_in[2];
    const float* boxes     = (const float*)d_in[n_in-10];
    const int*   labels    = (const int*)  d_in[n_in-9];
    const float* w_conv_s  = (const float*)d_in[n_in-8];
    const float* b_conv_s  = (const float*)d_in[n_in-7];
    const float* w_fc      = (const float*)d_in[n_in-6];
    const float* b_fc      = (const float*)d_in[n_in-5];
    const float* w_conv_c1 = (const float*)d_in[n_in-4];
    const float* b_conv_c1 = (const float*)d_in[n_in-3];
    const float* w_conv_c2 = (const float*)d_in[n_in-2];
    const float* b_conv_c2 = (const float*)d_in[n_in-1];
    float* out = (float*)d_out;

    k_roi   <<<64, 256>>>(fmap, boxes);
    k_conv  <<<dim3(6, 64), 224>>>(w_conv_s, b_conv_s, w_conv_c1, b_conv_c1, labels);
    k_fc    <<<1, 64>>>(w_fc, b_fc, labels, out);
    k_conv2 <<<64, 224>>>(w_conv_c2, b_conv_c2, labels);
    k_resize<<<dim3(480, 64), 320>>>(out);
}

// round 2
// speedup vs baseline: 1.3136x; 1.3136x over previous
#include <cuda_runtime.h>

#define M_TOT 64
#define HF 120
#define WF 160
#define C_IN 128
#define H_OUT 480
#define W_OUT 640
#define SZ_IMG (M_TOT * H_OUT * W_OUT)   // 19,660,800

typedef unsigned long long ull;

// Scratch (zero-initialized at load; padded borders stay zero forever).
__device__ float g_roi [M_TOT * C_IN * 16 * 16]; // [m][c][16][16], interior [1..14]
__device__ float g_h1  [M_TOT * 64   * 16 * 16]; // padded conv_c1 output
__device__ float g_gap2[M_TOT * 2 * C_IN];       // per-pos-half GAP sums (raw)
__device__ float g_cpart[M_TOT * 4 * 196];       // conv_c2 partials (no bias)
__device__ float g_ss  [M_TOT * 2];

__device__ __forceinline__ ull pack2(float lo, float hi) {
    ull r;
    asm("mov.b64 %0, {%1, %2};" : "=l"(r) : "f"(lo), "f"(hi));
    return r;
}
__device__ __forceinline__ void unpack2(ull v, float& lo, float& hi) {
    asm("mov.b64 {%0, %1}, %2;" : "=f"(lo), "=f"(hi) : "l"(v));
}
__device__ __forceinline__ void ffma2(ull& d, ull a, ull b) {
    asm("fma.rn.f32x2 %0, %1, %2, %3;" : "=l"(d) : "l"(a), "l"(b), "l"(d));
}

// ---------------------------------------------------------------------------
// K1: ROI align. grid (64,4), 256 threads.
// ---------------------------------------------------------------------------
__global__ void k_roi(const float* __restrict__ fmap, const float* __restrict__ boxes)
{
    int m = blockIdx.x;
    int b = m >> 4;
    __shared__ int   y0s[14], x0s[14];
    __shared__ float wys[14], wxs[14];

    float b0 = boxes[m*4+0], b1 = boxes[m*4+1], b2 = boxes[m*4+2], b3 = boxes[m*4+3];
    float y1 = 0.6f*b0, x1 = 0.6f*b1;
    float y2 = y1 + 0.1f + 0.3f*b2;
    float x2 = x1 + 0.1f + 0.3f*b3;

    int tid = threadIdx.x;
    if (tid < 14) {
        float t  = (tid + 0.5f) / 14.0f;
        float ys = (y1 + (y2 - y1) * t) * (float)(HF - 1);
        int y0 = (int)floorf(ys);
        if (y0 < 0) y0 = 0; if (y0 > HF-2) y0 = HF-2;
        y0s[tid] = y0;
        wys[tid] = fminf(fmaxf(ys - (float)y0, 0.f), 1.f);
    } else if (tid >= 32 && tid < 46) {
        int j = tid - 32;
        float t  = (j + 0.5f) / 14.0f;
        float xs = (x1 + (x2 - x1) * t) * (float)(WF - 1);
        int x0 = (int)floorf(xs);
        if (x0 < 0) x0 = 0; if (x0 > WF-2) x0 = WF-2;
        x0s[j] = x0;
        wxs[j] = fminf(fmaxf(xs - (float)x0, 0.f), 1.f);
    }
    __syncthreads();

    int seg = blockIdx.y;                     // channel quarter
    int base = seg * (C_IN/4) * 196;
    for (int rel = tid; rel < (C_IN/4) * 196; rel += blockDim.x) {
        int flat = base + rel;
        int c = flat / 196, r = flat % 196;
        int i = r / 14, j = r % 14;
        int y0 = y0s[i], x0 = x0s[j];
        float wy = wys[i], wx = wxs[j];
        const float* f = fmap + (((size_t)(b*C_IN + c) * HF + y0) * WF + x0);
        float v00 = f[0], v01 = f[1], v10 = f[WF], v11 = f[WF+1];
        float v = (1.f-wy)*((1.f-wx)*v00 + wx*v01) + wy*((1.f-wx)*v10 + wx*v11);
        g_roi[((m*C_IN + c)*16 + (i+1))*16 + (j+1)] = v;
    }
}

// ---------------------------------------------------------------------------
// K2: fused conv_s (+ReLU+GAP) and conv_c1 (+ReLU, padded store), FFMA2.
// grid (12, 64): blockIdx.x = u: co_unit = u/2 (0..3 conv_s co0=unit*32,
// 4..5 conv_c1), pos_half = u%2 (rows 0-6 / 7-13 => 98 positions).
// 128 threads; 100 compute threads own 8co(4 pairs) x 4pos tiles.
// ---------------------------------------------------------------------------
__global__ void __launch_bounds__(128) k_conv(
    const float* __restrict__ w_s_all,  const float* __restrict__ b_s_all,
    const float* __restrict__ w_c1_all, const float* __restrict__ b_c1_all,
    const int* __restrict__ labels)
{
    int u  = blockIdx.x;
    int m  = blockIdx.y;
    int lab = labels[m];
    int co_unit = u >> 1;
    int ph      = u & 1;
    bool is_s = (co_unit < 4);
    int co0 = is_s ? co_unit*32 : (co_unit-4)*32;
    const float* wg = is_s ? (w_s_all  + (size_t)lab*C_IN*C_IN*9 + (size_t)co0*C_IN*9)
                           : (w_c1_all + (size_t)lab*64*C_IN*9   + (size_t)co0*C_IN*9);
    const float* bg = is_s ? (b_s_all + lab*C_IN + co0) : (b_c1_all + lab*64 + co0);

    __shared__ float w_sh[16*9*32];      // [(ci*9+k)*32 + co_local]
    __shared__ float in_sh[16*9*17];     // [ci][r 0..8][x], stride 17
    __shared__ float red[32*25];         // GAP reduce

    int tid = threadIdx.x;
    int cg = tid / 25;                   // 0..3 (valid if tid<100)
    int pg = tid % 25;

    int posoff[4]; bool pval[4];
    #pragma unroll
    for (int uu = 0; uu < 4; ++uu) {
        int p = pg*4 + uu;
        pval[uu] = (p < 98);
        int pp = pval[uu] ? p : 0;
        posoff[uu] = (pp/14)*17 + (pp%14);
    }

    ull acc[4][4];
    #pragma unroll
    for (int o = 0; o < 4; ++o)
        #pragma unroll
        for (int uu = 0; uu < 4; ++uu) acc[o][uu] = 0ull;

    const float* roi_base = g_roi + (size_t)m * C_IN * 256 + (7*ph)*16;

    for (int chunk = 0; chunk < 8; ++chunk) {
        __syncthreads();
        // weights: src-linear coalesced, dest [(ci*9+k)*32 + co]
        for (int t = tid; t < 32*144; t += 128) {
            int co = t / 144, r = t % 144;      // r = ci*9+k
            w_sh[r*32 + co] = wg[(size_t)co*1152 + chunk*144 + r];
        }
        // input: 9 rows x 16 cols per ci, stride-17 smem
        for (int t = tid; t < 16*144; t += 128) {
            int ci = t / 144, rem = t % 144;
            int r = rem / 16, x = rem % 16;
            in_sh[(ci*9 + r)*17 + x] = roi_base[(chunk*16 + ci)*256 + r*16 + x];
        }
        __syncthreads();

        if (tid < 100) {
            #pragma unroll 2
            for (int ci = 0; ci < 16; ++ci) {
                const float* irow = &in_sh[ci*9*17];
                const float* wrow = &w_sh[ci*288 + cg*8];
                #pragma unroll
                for (int k = 0; k < 9; ++k) {
                    const int d = (k/3)*17 + (k%3);
                    ull wp[4];
                    #pragma unroll
                    for (int o = 0; o < 4; ++o)
                        wp[o] = *(const ull*)&wrow[k*32 + o*2];
                    #pragma unroll
                    for (int uu = 0; uu < 4; ++uu) {
                        float iv = irow[posoff[uu] + d];
                        ull ivp = pack2(iv, iv);
                        #pragma unroll
                        for (int o = 0; o < 4; ++o)
                            ffma2(acc[o][uu], wp[o], ivp);
                    }
                }
            }
        }
    }
    __syncthreads();

    if (is_s) {
        if (tid < 100) {
            #pragma unroll
            for (int o = 0; o < 4; ++o) {
                float blo = bg[cg*8 + o*2], bhi = bg[cg*8 + o*2 + 1];
                float slo = 0.f, shi = 0.f;
                #pragma unroll
                for (int uu = 0; uu < 4; ++uu) {
                    float lo, hi; unpack2(acc[o][uu], lo, hi);
                    if (pval[uu]) { slo += fmaxf(lo + blo, 0.f); shi += fmaxf(hi + bhi, 0.f); }
                }
                red[(cg*8 + o*2)*25 + pg]     = slo;
                red[(cg*8 + o*2 + 1)*25 + pg] = shi;
            }
        }
        __syncthreads();
        if (tid < 32) {
            float s = 0.f;
            #pragma unroll
            for (int i = 0; i < 25; ++i) s += red[tid*25 + i];
            g_gap2[(m*2 + ph)*C_IN + co0 + tid] = s;
        }
    } else if (tid < 100) {
        #pragma unroll
        for (int o = 0; o < 4; ++o) {
            float blo = bg[cg*8 + o*2], bhi = bg[cg*8 + o*2 + 1];
            #pragma unroll
            for (int uu = 0; uu < 4; ++uu) {
                if (!pval[uu]) continue;
                int p = pg*4 + uu;
                int gi = 7*ph + p/14, gj = p%14;
                float lo, hi; unpack2(acc[o][uu], lo, hi);
                int co_lo = co0 + cg*8 + o*2;
                g_h1[((m*64 + co_lo  )*16 + gi + 1)*16 + (gj + 1)] = fmaxf(lo + blo, 0.f);
                g_h1[((m*64 + co_lo+1)*16 + gi + 1)*16 + (gj + 1)] = fmaxf(hi + bhi, 0.f);
            }
        }
    }
}

// ---------------------------------------------------------------------------
// K3: FC head -> scale, shift. 1 block, 64 threads.
// ---------------------------------------------------------------------------
__global__ void k_fc(const float* __restrict__ w_fc, const float* __restrict__ b_fc,
                     const int* __restrict__ labels, float* __restrict__ out)
{
    int m = threadIdx.x;
    if (m >= M_TOT) return;
    int lab = labels[m];
    float s0 = b_fc[lab*2 + 0];
    float s1 = b_fc[lab*2 + 1];
    const float* w0 = w_fc + (size_t)(lab*2 + 0) * 128;
    const float* w1 = w_fc + (size_t)(lab*2 + 1) * 128;
    const float* ga = g_gap2 + (m*2    )*128;
    const float* gb = g_gap2 + (m*2 + 1)*128;
    for (int c = 0; c < 128; ++c) {
        float gv = (ga[c] + gb[c]) * (1.0f/196.0f);
        s0 = fmaf(gv, w0[c], s0);
        s1 = fmaf(gv, w1[c], s1);
    }
    g_ss[m*2 + 0] = s0;
    g_ss[m*2 + 1] = s1;
    out[(size_t)2*SZ_IMG + m]      = s0;   // scale
    out[(size_t)2*SZ_IMG + 64 + m] = s1;   // shift
}

// ---------------------------------------------------------------------------
// K4: conv_c2 (64 -> 1), ci-split. grid (64,4), 224 threads. Partials, no bias.
// ---------------------------------------------------------------------------
__global__ void k_conv2(const float* __restrict__ w2_all, const int* __restrict__ labels)
{
    int m = blockIdx.x;
    int s = blockIdx.y;          // ci chunk of 16
    int lab = labels[m];
    __shared__ float h_sh[16*16*17];   // [ci][r16][17]
    __shared__ float w2[144];
    int tid = threadIdx.x;

    for (int t = tid; t < 16*256; t += 224) {
        int ci = t / 256, rem = t % 256;
        int r = rem / 16, x = rem % 16;
        h_sh[ci*272 + r*17 + x] = g_h1[(size_t)(m*64 + s*16 + ci)*256 + rem];
    }
    for (int t = tid; t < 144; t += 224)
        w2[t] = w2_all[(size_t)lab*576 + s*144 + t];
    __syncthreads();

    if (tid < 196) {
        int i = tid / 14, j = tid % 14;
        float acc = 0.f;
        #pragma unroll 4
        for (int ci = 0; ci < 16; ++ci) {
            const float* hh = &h_sh[ci*272 + i*17 + j];
            const float* ww = &w2[ci*9];
            #pragma unroll
            for (int k = 0; k < 9; ++k)
                acc = fmaf(ww[k], hh[(k/3)*17 + (k%3)], acc);
        }
        g_cpart[(m*4 + s)*196 + tid] = acc;
    }
}

// ---------------------------------------------------------------------------
// K5: bilinear upsample + bias + scale/shift. grid (480,64), 160 threads, float4.
// ---------------------------------------------------------------------------
__global__ void k_resize(float* __restrict__ out,
                         const float* __restrict__ b2_all, const int* __restrict__ labels)
{
    int Y = blockIdx.x;
    int m = blockIdx.y;
    __shared__ float r0[14], r1[14];
    __shared__ float s_sc, s_sh, s_b2;
    int tid = threadIdx.x;

    float iy = (Y + 0.5f) * (14.0f/480.0f) - 0.5f;
    iy = fminf(fmaxf(iy, 0.f), 13.f);
    int y0 = (int)iy; if (y0 > 12) y0 = 12;
    float fy = iy - (float)y0;

    if (tid < 14) {
        float a = 0.f, b = 0.f;
        #pragma unroll
        for (int s = 0; s < 4; ++s) {
            a += g_cpart[(m*4 + s)*196 + y0*14 + tid];
            b += g_cpart[(m*4 + s)*196 + (y0+1)*14 + tid];
        }
        r0[tid] = a; r1[tid] = b;
    }
    if (tid == 14) s_sc = g_ss[m*2 + 0];
    if (tid == 15) s_sh = g_ss[m*2 + 1];
    if (tid == 16) s_b2 = b2_all[labels[m]];
    __syncthreads();

    float scale = s_sc, shift = s_sh, b2v = s_b2;
    size_t base = (size_t)m * H_OUT * W_OUT + (size_t)Y * W_OUT;

    float can4[4], dep4[4];
    #pragma unroll
    for (int uu = 0; uu < 4; ++uu) {
        int X = tid*4 + uu;
        float ix = (X + 0.5f) * (14.0f/640.0f) - 0.5f;
        ix = fminf(fmaxf(ix, 0.f), 13.f);
        int x0 = (int)ix; if (x0 > 12) x0 = 12;
        float fx = ix - (float)x0;
        float top = (1.f-fx)*r0[x0] + fx*r0[x0+1];
        float bot = (1.f-fx)*r1[x0] + fx*r1[x0+1];
        float can = (1.f-fy)*top + fy*bot + b2v;
        can4[uu] = can;
        dep4[uu] = fmaxf(can*scale + shift, 0.001f);
    }
    ((float4*)(out + base))[tid] = make_float4(dep4[0], dep4[1], dep4[2], dep4[3]);
    ((float4*)(out + SZ_IMG + base))[tid] = make_float4(can4[0], can4[1], can4[2], can4[3]);
}

// ---------------------------------------------------------------------------
extern "C" void kernel_launch(void* const* d_in, const int* in_sizes, int n_in,
                              void* d_out, int out_size)
{
    (void)in_sizes; (void)out_size;
    const float* fmap      = (const float*)d_in[2];
    const float* boxes     = (const float*)d_in[n_in-10];
    const int*   labels    = (const int*)  d_in[n_in-9];
    const float* w_conv_s  = (const float*)d_in[n_in-8];
    const float* b_conv_s  = (const float*)d_in[n_in-7];
    const float* w_fc      = (const float*)d_in[n_in-6];
    const float* b_fc      = (const float*)d_in[n_in-5];
    const float* w_conv_c1 = (const float*)d_in[n_in-4];
    const float* b_conv_c1 = (const float*)d_in[n_in-3];
    const float* w_conv_c2 = (const float*)d_in[n_in-2];
    const float* b_conv_c2 = (const float*)d_in[n_in-1];
    float* out = (float*)d_out;

    k_roi   <<<dim3(64, 4), 256>>>(fmap, boxes);
    k_conv  <<<dim3(12, 64), 128>>>(w_conv_s, b_conv_s, w_conv_c1, b_conv_c1, labels);
    k_fc    <<<1, 64>>>(w_fc, b_fc, labels, out);
    k_conv2 <<<dim3(64, 4), 224>>>(w_conv_c2, labels);
    k_resize<<<dim3(480, 64), 160>>>(out, b_conv_c2, labels);
}

// round 3
// speedup vs baseline: 1.8067x; 1.3754x over previous
#include <cuda_runtime.h>

#define M_TOT 64
#define HF 120
#define WF 160
#define C_IN 128
#define H_OUT 480
#define W_OUT 640
#define SZ_IMG (M_TOT * H_OUT * W_OUT)   // 19,660,800

typedef unsigned long long ull;

// Scratch (zero-initialized at load; padded borders stay zero forever).
__device__ float g_roi [M_TOT * C_IN * 16 * 16]; // [m][c][16][16], interior [1..14]
__device__ float g_h1  [M_TOT * 64   * 16 * 16]; // padded conv_c1 output
__device__ float g_gap2[M_TOT * 2 * C_IN];       // per-pos-half GAP sums (raw)
__device__ float g_cpart[M_TOT * 8 * 196];       // conv_c2 partials (no bias)
__device__ float g_ss  [M_TOT * 2];

__device__ __forceinline__ void unpack2(ull v, float& lo, float& hi) {
    asm("mov.b64 {%0, %1}, %2;" : "=f"(lo), "=f"(hi) : "l"(v));
}
__device__ __forceinline__ void ffma2(ull& d, ull a, ull b) {
    asm("fma.rn.f32x2 %0, %1, %2, %3;" : "=l"(d) : "l"(a), "l"(b), "l"(d));
}

// ---------------------------------------------------------------------------
// K1: ROI align. grid (64,8), 256 threads.
// ---------------------------------------------------------------------------
__global__ void k_roi(const float* __restrict__ fmap, const float* __restrict__ boxes)
{
    int m = blockIdx.x;
    int b = m >> 4;
    __shared__ int   y0s[14], x0s[14];
    __shared__ float wys[14], wxs[14];

    float b0 = boxes[m*4+0], b1 = boxes[m*4+1], b2 = boxes[m*4+2], b3 = boxes[m*4+3];
    float y1 = 0.6f*b0, x1 = 0.6f*b1;
    float y2 = y1 + 0.1f + 0.3f*b2;
    float x2 = x1 + 0.1f + 0.3f*b3;

    int tid = threadIdx.x;
    if (tid < 14) {
        float t  = (tid + 0.5f) / 14.0f;
        float ys = (y1 + (y2 - y1) * t) * (float)(HF - 1);
        int y0 = (int)floorf(ys);
        if (y0 < 0) y0 = 0; if (y0 > HF-2) y0 = HF-2;
        y0s[tid] = y0;
        wys[tid] = fminf(fmaxf(ys - (float)y0, 0.f), 1.f);
    } else if (tid >= 32 && tid < 46) {
        int j = tid - 32;
        float t  = (j + 0.5f) / 14.0f;
        float xs = (x1 + (x2 - x1) * t) * (float)(WF - 1);
        int x0 = (int)floorf(xs);
        if (x0 < 0) x0 = 0; if (x0 > WF-2) x0 = WF-2;
        x0s[j] = x0;
        wxs[j] = fminf(fmaxf(xs - (float)x0, 0.f), 1.f);
    }
    __syncthreads();

    int seg = blockIdx.y;                     // channel eighth
    int base = seg * (C_IN/8) * 196;
    for (int rel = tid; rel < (C_IN/8) * 196; rel += blockDim.x) {
        int flat = base + rel;
        int c = flat / 196, r = flat % 196;
        int i = r / 14, j = r % 14;
        int y0 = y0s[i], x0 = x0s[j];
        float wy = wys[i], wx = wxs[j];
        const float* f = fmap + (((size_t)(b*C_IN + c) * HF + y0) * WF + x0);
        float v00 = f[0], v01 = f[1], v10 = f[WF], v11 = f[WF+1];
        float v = (1.f-wy)*((1.f-wx)*v00 + wx*v01) + wy*((1.f-wx)*v10 + wx*v11);
        g_roi[((m*C_IN + c)*16 + (i+1))*16 + (j+1)] = v;
    }
}

// ---------------------------------------------------------------------------
// K2: fused conv_s (+ReLU+GAP) and conv_c1 (+ReLU, padded store).
// FFMA2 with the ci-reduction in the pair lanes (natural LDS.64 on both
// operands, no packing). grid (12, 64): u = co_unit*2 + pos_half.
// 128 threads; 112 compute threads own 8co x (1row x 4x) tiles.
// ---------------------------------------------------------------------------
__global__ void __launch_bounds__(128, 5) k_conv(
    const float* __restrict__ w_s_all,  const float* __restrict__ b_s_all,
    const float* __restrict__ w_c1_all, const float* __restrict__ b_c1_all,
    const int* __restrict__ labels)
{
    int u  = blockIdx.x;
    int m  = blockIdx.y;
    int lab = labels[m];
    int co_unit = u >> 1;
    int ph      = u & 1;
    bool is_s = (co_unit < 4);
    int co0 = is_s ? co_unit*32 : (co_unit-4)*32;
    const float* wg = is_s ? (w_s_all  + (size_t)lab*C_IN*C_IN*9 + (size_t)co0*C_IN*9)
                           : (w_c1_all + (size_t)lab*64*C_IN*9   + (size_t)co0*C_IN*9);
    const float* bg = is_s ? (b_s_all + lab*C_IN + co0) : (b_c1_all + lab*64 + co0);

    __shared__ float w_sh [9*32*18];     // [k][co][ci], ci stride 1, co stride 18
    __shared__ float in_sh[9*18*18];     // [irow*18+ix][ci], ci stride 1, pos stride 18
    __shared__ float red  [32*28];       // GAP reduce

    int tid = threadIdx.x;
    int cg  = tid / 28;                  // 0..3 co group (valid if tid<112)
    int pg  = tid % 28;
    int row = pg >> 2;                   // 0..6 output row within half
    int x0q = (pg & 3) * 4;              // 0,4,8,12

    // zero the guard x-slots (ix = 16,17) once; never overwritten
    for (int t = tid; t < 9*2*18; t += 128) {
        int irow = t / 36, rem = t % 36;
        int ix = 16 + rem / 18, ci = rem % 18;
        in_sh[(irow*18 + ix)*18 + ci] = 0.f;
    }

    ull acc[8][4];
    #pragma unroll
    for (int o = 0; o < 8; ++o)
        #pragma unroll
        for (int p = 0; p < 4; ++p) acc[o][p] = 0ull;

    const float* roi_base = g_roi + (size_t)m * C_IN * 256 + ph*112;

    for (int chunk = 0; chunk < 8; ++chunk) {
        __syncthreads();
        // weights: wg[co*1152 + chunk*144 + (ci*9+k)] -> w_sh[k*576 + co*18 + ci]
        for (int t = tid; t < 1152; t += 128) {
            int co = t / 36;
            int r4 = (t % 36) * 4;
            float4 v = *(const float4*)&wg[(size_t)co*1152 + chunk*144 + r4];
            #pragma unroll
            for (int q = 0; q < 4; ++q) {
                int r = r4 + q, ci = r / 9, k = r % 9;
                w_sh[k*576 + co*18 + ci] = ((const float*)&v)[q];
            }
        }
        // input: 16 ci x 9 rows x 16 x -> in_sh[(r*18+x)*18 + ci]
        for (int t = tid; t < 576; t += 128) {
            int ci = t / 36;
            int rem4 = (t % 36) * 4;
            float4 v = *(const float4*)&roi_base[(chunk*16 + ci)*256 + rem4];
            int r = rem4 >> 4, x0 = rem4 & 15;
            #pragma unroll
            for (int q = 0; q < 4; ++q)
                in_sh[(r*18 + x0 + q)*18 + ci] = ((const float*)&v)[q];
        }
        __syncthreads();

        if (tid < 112) {
            #pragma unroll 1
            for (int cp = 0; cp < 8; ++cp) {
                #pragma unroll
                for (int k = 0; k < 9; ++k) {
                    const int kr = k / 3, kc = k % 3;
                    const float* ibase = &in_sh[((row + kr)*18 + x0q + kc)*18 + cp*2];
                    ull ip[4];
                    #pragma unroll
                    for (int p = 0; p < 4; ++p)
                        ip[p] = *(const ull*)&ibase[p*18];
                    const float* wbase = &w_sh[k*576 + cg*8*18 + cp*2];
                    #pragma unroll
                    for (int o = 0; o < 8; ++o) {
                        ull wp = *(const ull*)&wbase[o*18];
                        #pragma unroll
                        for (int p = 0; p < 4; ++p)
                            ffma2(acc[o][p], wp, ip[p]);
                    }
                }
            }
        }
    }
    __syncthreads();

    if (is_s) {
        if (tid < 112) {
            #pragma unroll
            for (int o = 0; o < 8; ++o) {
                float bv = bg[cg*8 + o];
                float s = 0.f;
                #pragma unroll
                for (int p = 0; p < 4; ++p) {
                    float lo, hi; unpack2(acc[o][p], lo, hi);
                    if (x0q + p < 14) s += fmaxf(lo + hi + bv, 0.f);
                }
                red[(cg*8 + o)*28 + pg] = s;
            }
        }
        __syncthreads();
        if (tid < 32) {
            float s = 0.f;
            #pragma unroll
            for (int i = 0; i < 28; ++i) s += red[tid*28 + i];
            g_gap2[(m*2 + ph)*C_IN + co0 + tid] = s;
        }
    } else if (tid < 112) {
        int gi = 7*ph + row;
        #pragma unroll
        for (int o = 0; o < 8; ++o) {
            float bv = bg[cg*8 + o];
            int co = co0 + cg*8 + o;
            #pragma unroll
            for (int p = 0; p < 4; ++p) {
                int x = x0q + p;
                if (x < 14) {
                    float lo, hi; unpack2(acc[o][p], lo, hi);
                    g_h1[((m*64 + co)*16 + gi + 1)*16 + (x + 1)] =
                        fmaxf(lo + hi + bv, 0.f);
                }
            }
        }
    }
}

// ---------------------------------------------------------------------------
// K3: FC head -> scale, shift. grid 64, 32 threads (warp per instance).
// ---------------------------------------------------------------------------
__global__ void k_fc(const float* __restrict__ w_fc, const float* __restrict__ b_fc,
                     const int* __restrict__ labels, float* __restrict__ out)
{
    int m = blockIdx.x;
    int lane = threadIdx.x;
    int lab = labels[m];
    float4 ga = *(const float4*)&g_gap2[m*256 + lane*4];
    float4 gb = *(const float4*)&g_gap2[m*256 + 128 + lane*4];
    float4 w0 = *(const float4*)&w_fc[(size_t)(lab*2    )*128 + lane*4];
    float4 w1 = *(const float4*)&w_fc[(size_t)(lab*2 + 1)*128 + lane*4];
    float g0 = (ga.x + gb.x) * (1.0f/196.0f);
    float g1 = (ga.y + gb.y) * (1.0f/196.0f);
    float g2 = (ga.z + gb.z) * (1.0f/196.0f);
    float g3 = (ga.w + gb.w) * (1.0f/196.0f);
    float s0 = g0*w0.x + g1*w0.y + g2*w0.z + g3*w0.w;
    float s1 = g0*w1.x + g1*w1.y + g2*w1.z + g3*w1.w;
    #pragma unroll
    for (int d = 16; d > 0; d >>= 1) {
        s0 += __shfl_xor_sync(0xffffffffu, s0, d);
        s1 += __shfl_xor_sync(0xffffffffu, s1, d);
    }
    if (lane == 0) {
        s0 += b_fc[lab*2 + 0];
        s1 += b_fc[lab*2 + 1];
        g_ss[m*2 + 0] = s0;
        g_ss[m*2 + 1] = s1;
        out[(size_t)2*SZ_IMG + m]      = s0;   // scale
        out[(size_t)2*SZ_IMG + 64 + m] = s1;   // shift
    }
}

// ---------------------------------------------------------------------------
// K4: conv_c2 (64 -> 1), ci-split by 8. grid (64,8), 256 threads. Partials.
// ---------------------------------------------------------------------------
__global__ void k_conv2(const float* __restrict__ w2_all, const int* __restrict__ labels)
{
    int m = blockIdx.x;
    int s = blockIdx.y;          // ci chunk of 8
    int lab = labels[m];
    __shared__ float h_sh[8*16*17];   // [ci][r16][17]
    __shared__ float w2[72];
    int tid = threadIdx.x;

    for (int t = tid; t < 512; t += 256) {
        int ci = t / 64, rem4 = (t % 64) * 4;
        float4 v = *(const float4*)&g_h1[(size_t)(m*64 + s*8 + ci)*256 + rem4];
        int r = rem4 >> 4, x0 = rem4 & 15;
        #pragma unroll
        for (int q = 0; q < 4; ++q)
            h_sh[ci*272 + r*17 + x0 + q] = ((const float*)&v)[q];
    }
    if (tid < 72)
        w2[tid] = w2_all[(size_t)lab*576 + s*72 + tid];
    __syncthreads();

    if (tid < 196) {
        int i = tid / 14, j = tid % 14;
        float acc = 0.f;
        #pragma unroll
        for (int ci = 0; ci < 8; ++ci) {
            const float* hh = &h_sh[ci*272 + i*17 + j];
            const float* ww = &w2[ci*9];
            #pragma unroll
            for (int k = 0; k < 9; ++k)
                acc = fmaf(ww[k], hh[(k/3)*17 + (k%3)], acc);
        }
        g_cpart[(m*8 + s)*196 + tid] = acc;
    }
}

// ---------------------------------------------------------------------------
// K5: bilinear upsample + bias + scale/shift. grid (480,64), 160 threads, float4.
// ---------------------------------------------------------------------------
__global__ void k_resize(float* __restrict__ out,
                         const float* __restrict__ b2_all, const int* __restrict__ labels)
{
    int Y = blockIdx.x;
    int m = blockIdx.y;
    __shared__ float r0[14], r1[14];
    __shared__ float s_sc, s_sh, s_b2;
    int tid = threadIdx.x;

    float iy = (Y + 0.5f) * (14.0f/480.0f) - 0.5f;
    iy = fminf(fmaxf(iy, 0.f), 13.f);
    int y0 = (int)iy; if (y0 > 12) y0 = 12;
    float fy = iy - (float)y0;

    if (tid < 14) {
        float a = 0.f, b = 0.f;
        #pragma unroll
        for (int s = 0; s < 8; ++s) {
            a += g_cpart[(m*8 + s)*196 + y0*14 + tid];
            b += g_cpart[(m*8 + s)*196 + (y0+1)*14 + tid];
        }
        r0[tid] = a; r1[tid] = b;
    }
    if (tid == 14) s_sc = g_ss[m*2 + 0];
    if (tid == 15) s_sh = g_ss[m*2 + 1];
    if (tid == 16) s_b2 = b2_all[labels[m]];
    __syncthreads();

    float scale = s_sc, shift = s_sh, b2v = s_b2;
    size_t base = (size_t)m * H_OUT * W_OUT + (size_t)Y * W_OUT;

    float can4[4], dep4[4];
    #pragma unroll
    for (int uu = 0; uu < 4; ++uu) {
        int X = tid*4 + uu;
        float ix = (X + 0.5f) * (14.0f/640.0f) - 0.5f;
        ix = fminf(fmaxf(ix, 0.f), 13.f);
        int x0 = (int)ix; if (x0 > 12) x0 = 12;
        float fx = ix - (float)x0;
        float top = (1.f-fx)*r0[x0] + fx*r0[x0+1];
        float bot = (1.f-fx)*r1[x0] + fx*r1[x0+1];
        float can = (1.f-fy)*top + fy*bot + b2v;
        can4[uu] = can;
        dep4[uu] = fmaxf(can*scale + shift, 0.001f);
    }
    ((float4*)(out + base))[tid] = make_float4(dep4[0], dep4[1], dep4[2], dep4[3]);
    ((float4*)(out + SZ_IMG + base))[tid] = make_float4(can4[0], can4[1], can4[2], can4[3]);
}

// ---------------------------------------------------------------------------
extern "C" void kernel_launch(void* const* d_in, const int* in_sizes, int n_in,
                              void* d_out, int out_size)
{
    (void)in_sizes; (void)out_size;
    const float* fmap      = (const float*)d_in[2];
    const float* boxes     = (const float*)d_in[n_in-10];
    const int*   labels    = (const int*)  d_in[n_in-9];
    const float* w_conv_s  = (const float*)d_in[n_in-8];
    const float* b_conv_s  = (const float*)d_in[n_in-7];
    const float* w_fc      = (const float*)d_in[n_in-6];
    const float* b_fc      = (const float*)d_in[n_in-5];
    const float* w_conv_c1 = (const float*)d_in[n_in-4];
    const float* b_conv_c1 = (const float*)d_in[n_in-3];
    const float* w_conv_c2 = (const float*)d_in[n_in-2];
    const float* b_conv_c2 = (const float*)d_in[n_in-1];
    float* out = (float*)d_out;

    k_roi   <<<dim3(64, 8), 256>>>(fmap, boxes);
    k_conv  <<<dim3(12, 64), 128>>>(w_conv_s, b_conv_s, w_conv_c1, b_conv_c1, labels);
    k_fc    <<<64, 32>>>(w_fc, b_fc, labels, out);
    k_conv2 <<<dim3(64, 8), 256>>>(w_conv_c2, labels);
    k_resize<<<dim3(480, 64), 160>>>(out, b_conv_c2, labels);
}

// round 4
// speedup vs baseline: 1.9700x; 1.0904x over previous
#include <cuda_runtime.h>

#define M_TOT 64
#define HF 120
#define WF 160
#define C_IN 128
#define H_OUT 480
#define W_OUT 640
#define SZ_IMG (M_TOT * H_OUT * W_OUT)   // 19,660,800
#define N_EXP 13
#define WT_PER 5184                      // 9*32*18 floats per (unit,chunk)

typedef unsigned long long ull;

// Scratch (zero-initialized at load; padded slots stay zero forever).
__device__ __align__(16) float g_wT  [N_EXP * 6 * 8 * WT_PER];  // [lab][unit][chunk][k][co32][ci18]
__device__ __align__(16) float g_roiT[M_TOT * 8 * 16 * 324];    // [m][chunk][row16][x18][ci18]
__device__ __align__(16) float g_h1  [M_TOT * 64 * 16 * 16];    // padded conv_c1 output
__device__ float g_gap2[M_TOT * 2 * C_IN];
__device__ float g_cpart[M_TOT * 8 * 196];
__device__ float g_ss  [M_TOT * 2];

__device__ __forceinline__ void unpack2(ull v, float& lo, float& hi) {
    asm("mov.b64 {%0, %1}, %2;" : "=f"(lo), "=f"(hi) : "l"(v));
}
__device__ __forceinline__ void ffma2(ull& d, ull a, ull b) {
    asm("fma.rn.f32x2 %0, %1, %2, %3;" : "=l"(d) : "l"(a), "l"(b), "l"(d));
}

// ---------------------------------------------------------------------------
// K0: weight pre-transpose into the smem-ready layout. grid (48, 13), 256 thr.
// ---------------------------------------------------------------------------
__global__ void k_wt(const float* __restrict__ w_s, const float* __restrict__ w_c1)
{
    int uc   = blockIdx.x;            // unit*8 + chunk
    int lab  = blockIdx.y;
    int unit = uc >> 3, chunk = uc & 7;
    const float* wb = (unit < 4)
        ? w_s  + ((size_t)lab*128 + unit*32)     * 1152
        : w_c1 + ((size_t)lab*64  + (unit-4)*32) * 1152;
    float* dst = g_wT + ((size_t)(lab*6 + unit)*8 + chunk) * WT_PER;
    for (int d = threadIdx.x; d < WT_PER; d += 256) {
        int k = d / 576, rem = d % 576, co = rem / 18, ci = rem % 18;
        float v = 0.f;
        if (ci < 16) v = wb[(size_t)co*1152 + chunk*144 + ci*9 + k];
        dst[d] = v;
    }
}

// ---------------------------------------------------------------------------
// K1: ROI align, writing the conv-friendly transposed layout. grid (64,8).
// ---------------------------------------------------------------------------
__global__ void k_roi(const float* __restrict__ fmap, const float* __restrict__ boxes)
{
    int m = blockIdx.x;
    int b = m >> 4;
    __shared__ int   y0s[14], x0s[14];
    __shared__ float wys[14], wxs[14];

    float b0 = boxes[m*4+0], b1 = boxes[m*4+1], b2 = boxes[m*4+2], b3 = boxes[m*4+3];
    float y1 = 0.6f*b0, x1 = 0.6f*b1;
    float y2 = y1 + 0.1f + 0.3f*b2;
    float x2 = x1 + 0.1f + 0.3f*b3;

    int tid = threadIdx.x;
    if (tid < 14) {
        float t  = (tid + 0.5f) / 14.0f;
        float ys = (y1 + (y2 - y1) * t) * (float)(HF - 1);
        int y0 = (int)floorf(ys);
        if (y0 < 0) y0 = 0; if (y0 > HF-2) y0 = HF-2;
        y0s[tid] = y0;
        wys[tid] = fminf(fmaxf(ys - (float)y0, 0.f), 1.f);
    } else if (tid >= 32 && tid < 46) {
        int j = tid - 32;
        float t  = (j + 0.5f) / 14.0f;
        float xs = (x1 + (x2 - x1) * t) * (float)(WF - 1);
        int x0 = (int)floorf(xs);
        if (x0 < 0) x0 = 0; if (x0 > WF-2) x0 = WF-2;
        x0s[j] = x0;
        wxs[j] = fminf(fmaxf(xs - (float)x0, 0.f), 1.f);
    }
    __syncthreads();

    int seg = blockIdx.y;                     // channel eighth
    int base = seg * (C_IN/8) * 196;
    for (int rel = tid; rel < (C_IN/8) * 196; rel += blockDim.x) {
        int flat = base + rel;
        int c = flat / 196, r = flat % 196;
        int i = r / 14, j = r % 14;
        int y0 = y0s[i], x0 = x0s[j];
        float wy = wys[i], wx = wxs[j];
        const float* f = fmap + (((size_t)(b*C_IN + c) * HF + y0) * WF + x0);
        float v00 = f[0], v01 = f[1], v10 = f[WF], v11 = f[WF+1];
        float v = (1.f-wy)*((1.f-wx)*v00 + wx*v01) + wy*((1.f-wx)*v10 + wx*v11);
        g_roiT[(((size_t)m*8 + (c>>4))*16 + (i+1))*324 + (j+1)*18 + (c&15)] = v;
    }
}

// ---------------------------------------------------------------------------
// K2: fused conv_s (+ReLU+GAP) and conv_c1 (+ReLU). FFMA2 over ci-pairs,
// staging = pure float4 memcpy from pre-transposed buffers.
// grid (12, 64): u = co_unit*2 + pos_half. 128 threads, 112 compute.
// ---------------------------------------------------------------------------
__global__ void __launch_bounds__(128, 5) k_conv(
    const float* __restrict__ b_s_all, const float* __restrict__ b_c1_all,
    const int* __restrict__ labels)
{
    int u  = blockIdx.x;
    int m  = blockIdx.y;
    int lab = labels[m];
    int co_unit = u >> 1;
    int ph      = u & 1;
    bool is_s = (co_unit < 4);
    int co0 = is_s ? co_unit*32 : (co_unit-4)*32;
    const float* bg = is_s ? (b_s_all + lab*C_IN + co0) : (b_c1_all + lab*64 + co0);

    __shared__ __align__(16) float w_sh [WT_PER];   // [k][co32][ci18]
    __shared__ __align__(16) float in_sh[9*18*18];  // [(row*18+x)][ci18]
    __shared__ float red[32*28];

    int tid = threadIdx.x;
    int cg  = tid / 28;
    int pg  = tid % 28;
    int row = pg >> 2;
    int x0q = (pg & 3) * 4;

    ull acc[8][4];
    #pragma unroll
    for (int o = 0; o < 8; ++o)
        #pragma unroll
        for (int p = 0; p < 4; ++p) acc[o][p] = 0ull;

    const float* wsrc = g_wT + ((size_t)(lab*6 + co_unit)*8) * WT_PER;
    const float* isrc = g_roiT + ((size_t)m*8) * WT_PER + 2268*ph;  // 7*324*ph

    for (int chunk = 0; chunk < 8; ++chunk) {
        __syncthreads();
        const float4* ws = (const float4*)(wsrc + chunk*WT_PER);
        #pragma unroll
        for (int t = 0; t < 11; ++t) {
            int idx = tid + t*128;
            if (idx < 1296) ((float4*)w_sh)[idx] = ws[idx];
        }
        const float4* is = (const float4*)(isrc + chunk*WT_PER);
        #pragma unroll
        for (int t = 0; t < 6; ++t) {
            int idx = tid + t*128;
            if (idx < 729) ((float4*)in_sh)[idx] = is[idx];
        }
        __syncthreads();

        if (tid < 112) {
            #pragma unroll 1
            for (int cp = 0; cp < 8; ++cp) {
                #pragma unroll
                for (int k = 0; k < 9; ++k) {
                    const int kr = k / 3, kc = k % 3;
                    const float* ibase = &in_sh[((row + kr)*18 + x0q + kc)*18 + cp*2];
                    ull ip[4];
                    #pragma unroll
                    for (int p = 0; p < 4; ++p)
                        ip[p] = *(const ull*)&ibase[p*18];
                    const float* wbase = &w_sh[k*576 + cg*8*18 + cp*2];
                    #pragma unroll
                    for (int o = 0; o < 8; ++o) {
                        ull wp = *(const ull*)&wbase[o*18];
                        #pragma unroll
                        for (int p = 0; p < 4; ++p)
                            ffma2(acc[o][p], wp, ip[p]);
                    }
                }
            }
        }
    }
    __syncthreads();

    if (is_s) {
        if (tid < 112) {
            #pragma unroll
            for (int o = 0; o < 8; ++o) {
                float bv = bg[cg*8 + o];
                float s = 0.f;
                #pragma unroll
                for (int p = 0; p < 4; ++p) {
                    float lo, hi; unpack2(acc[o][p], lo, hi);
                    if (x0q + p < 14) s += fmaxf(lo + hi + bv, 0.f);
                }
                red[(cg*8 + o)*28 + pg] = s;
            }
        }
        __syncthreads();
        if (tid < 32) {
            float s = 0.f;
            #pragma unroll
            for (int i = 0; i < 28; ++i) s += red[tid*28 + i];
            g_gap2[(m*2 + ph)*C_IN + co0 + tid] = s;
        }
    } else if (tid < 112) {
        int gi = 7*ph + row;
        #pragma unroll
        for (int o = 0; o < 8; ++o) {
            float bv = bg[cg*8 + o];
            int co = co0 + cg*8 + o;
            #pragma unroll
            for (int p = 0; p < 4; ++p) {
                int x = x0q + p;
                if (x < 14) {
                    float lo, hi; unpack2(acc[o][p], lo, hi);
                    g_h1[((m*64 + co)*16 + gi + 1)*16 + (x + 1)] =
                        fmaxf(lo + hi + bv, 0.f);
                }
            }
        }
    }
}

// ---------------------------------------------------------------------------
// K3: FC head -> scale, shift. grid 64, 32 threads (warp per instance).
// ---------------------------------------------------------------------------
__global__ void k_fc(const float* __restrict__ w_fc, const float* __restrict__ b_fc,
                     const int* __restrict__ labels, float* __restrict__ out)
{
    int m = blockIdx.x;
    int lane = threadIdx.x;
    int lab = labels[m];
    float4 ga = *(const float4*)&g_gap2[m*256 + lane*4];
    float4 gb = *(const float4*)&g_gap2[m*256 + 128 + lane*4];
    float4 w0 = *(const float4*)&w_fc[(size_t)(lab*2    )*128 + lane*4];
    float4 w1 = *(const float4*)&w_fc[(size_t)(lab*2 + 1)*128 + lane*4];
    float g0 = (ga.x + gb.x) * (1.0f/196.0f);
    float g1 = (ga.y + gb.y) * (1.0f/196.0f);
    float g2 = (ga.z + gb.z) * (1.0f/196.0f);
    float g3 = (ga.w + gb.w) * (1.0f/196.0f);
    float s0 = g0*w0.x + g1*w0.y + g2*w0.z + g3*w0.w;
    float s1 = g0*w1.x + g1*w1.y + g2*w1.z + g3*w1.w;
    #pragma unroll
    for (int d = 16; d > 0; d >>= 1) {
        s0 += __shfl_xor_sync(0xffffffffu, s0, d);
        s1 += __shfl_xor_sync(0xffffffffu, s1, d);
    }
    if (lane == 0) {
        s0 += b_fc[lab*2 + 0];
        s1 += b_fc[lab*2 + 1];
        g_ss[m*2 + 0] = s0;
        g_ss[m*2 + 1] = s1;
        out[(size_t)2*SZ_IMG + m]      = s0;   // scale
        out[(size_t)2*SZ_IMG + 64 + m] = s1;   // shift
    }
}

// ---------------------------------------------------------------------------
// K4: conv_c2 (64 -> 1), ci-split by 8. grid (64,8), 256 threads. Partials.
// ---------------------------------------------------------------------------
__global__ void k_conv2(const float* __restrict__ w2_all, const int* __restrict__ labels)
{
    int m = blockIdx.x;
    int s = blockIdx.y;          // ci chunk of 8
    int lab = labels[m];
    __shared__ float h_sh[8*16*17];   // [ci][r16][17]
    __shared__ float w2[72];
    int tid = threadIdx.x;

    for (int t = tid; t < 512; t += 256) {
        int ci = t / 64, rem4 = (t % 64) * 4;
        float4 v = *(const float4*)&g_h1[(size_t)(m*64 + s*8 + ci)*256 + rem4];
        int r = rem4 >> 4, x0 = rem4 & 15;
        #pragma unroll
        for (int q = 0; q < 4; ++q)
            h_sh[ci*272 + r*17 + x0 + q] = ((const float*)&v)[q];
    }
    if (tid < 72)
        w2[tid] = w2_all[(size_t)lab*576 + s*72 + tid];
    __syncthreads();

    if (tid < 196) {
        int i = tid / 14, j = tid % 14;
        float acc = 0.f;
        #pragma unroll
        for (int ci = 0; ci < 8; ++ci) {
            const float* hh = &h_sh[ci*272 + i*17 + j];
            const float* ww = &w2[ci*9];
            #pragma unroll
            for (int k = 0; k < 9; ++k)
                acc = fmaf(ww[k], hh[(k/3)*17 + (k%3)], acc);
        }
        g_cpart[(m*8 + s)*196 + tid] = acc;
    }
}

// ---------------------------------------------------------------------------
// K5: bilinear upsample + bias + scale/shift. grid (480,64), 160 threads, float4.
// ---------------------------------------------------------------------------
__global__ void k_resize(float* __restrict__ out,
                         const float* __restrict__ b2_all, const int* __restrict__ labels)
{
    int Y = blockIdx.x;
    int m = blockIdx.y;
    __shared__ float r0[14], r1[14];
    __shared__ float s_sc, s_sh, s_b2;
    int tid = threadIdx.x;

    float iy = (Y + 0.5f) * (14.0f/480.0f) - 0.5f;
    iy = fminf(fmaxf(iy, 0.f), 13.f);
    int y0 = (int)iy; if (y0 > 12) y0 = 12;
    float fy = iy - (float)y0;

    if (tid < 14) {
        float a = 0.f, b = 0.f;
        #pragma unroll
        for (int s = 0; s < 8; ++s) {
            a += g_cpart[(m*8 + s)*196 + y0*14 + tid];
            b += g_cpart[(m*8 + s)*196 + (y0+1)*14 + tid];
        }
        r0[tid] = a; r1[tid] = b;
    }
    if (tid == 14) s_sc = g_ss[m*2 + 0];
    if (tid == 15) s_sh = g_ss[m*2 + 1];
    if (tid == 16) s_b2 = b2_all[labels[m]];
    __syncthreads();

    float scale = s_sc, shift = s_sh, b2v = s_b2;
    size_t base = (size_t)m * H_OUT * W_OUT + (size_t)Y * W_OUT;

    float can4[4], dep4[4];
    #pragma unroll
    for (int uu = 0; uu < 4; ++uu) {
        int X = tid*4 + uu;
        float ix = (X + 0.5f) * (14.0f/640.0f) - 0.5f;
        ix = fminf(fmaxf(ix, 0.f), 13.f);
        int x0 = (int)ix; if (x0 > 12) x0 = 12;
        float fx = ix - (float)x0;
        float top = (1.f-fx)*r0[x0] + fx*r0[x0+1];
        float bot = (1.f-fx)*r1[x0] + fx*r1[x0+1];
        float can = (1.f-fy)*top + fy*bot + b2v;
        can4[uu] = can;
        dep4[uu] = fmaxf(can*scale + shift, 0.001f);
    }
    ((float4*)(out + base))[tid] = make_float4(dep4[0], dep4[1], dep4[2], dep4[3]);
    ((float4*)(out + SZ_IMG + base))[tid] = make_float4(can4[0], can4[1], can4[2], can4[3]);
}

// ---------------------------------------------------------------------------
extern "C" void kernel_launch(void* const* d_in, const int* in_sizes, int n_in,
                              void* d_out, int out_size)
{
    (void)in_sizes; (void)out_size;
    const float* fmap      = (const float*)d_in[2];
    const float* boxes     = (const float*)d_in[n_in-10];
    const int*   labels    = (const int*)  d_in[n_in-9];
    const float* w_conv_s  = (const float*)d_in[n_in-8];
    const float* b_conv_s  = (const float*)d_in[n_in-7];
    const float* w_fc      = (const float*)d_in[n_in-6];
    const float* b_fc      = (const float*)d_in[n_in-5];
    const float* w_conv_c1 = (const float*)d_in[n_in-4];
    const float* b_conv_c1 = (const float*)d_in[n_in-3];
    const float* w_conv_c2 = (const float*)d_in[n_in-2];
    const float* b_conv_c2 = (const float*)d_in[n_in-1];
    float* out = (float*)d_out;

    k_wt    <<<dim3(48, 13), 256>>>(w_conv_s, w_conv_c1);
    k_roi   <<<dim3(64, 8), 256>>>(fmap, boxes);
    k_conv  <<<dim3(12, 64), 128>>>(b_conv_s, b_conv_c1, labels);
    k_fc    <<<64, 32>>>(w_fc, b_fc, labels, out);
    k_conv2 <<<dim3(64, 8), 256>>>(w_conv_c2, labels);
    k_resize<<<dim3(480, 64), 160>>>(out, b_conv_c2, labels);
}

// round 5
// speedup vs baseline: 2.0753x; 1.0534x over previous
#include <cuda_runtime.h>

#define M_TOT 64
#define HF 120
#define WF 160
#define C_IN 128
#define H_OUT 480
#define W_OUT 640
#define SZ_IMG (M_TOT * H_OUT * W_OUT)   // 19,660,800
#define N_EXP 13
#define WT2 4608                         // 9k*4cg*8cp*8o*2 floats per (unit,chunk)
#define ROI_PER 5184                     // 16*324 floats per (m,chunk)

typedef unsigned long long ull;

// Scratch (zero-initialized at load; padded slots stay zero forever).
__device__ __align__(16) float g_wT  [N_EXP * 6 * 8 * WT2];   // [lab][unit][chunk][k][cg][cp][o2]
__device__ __align__(16) float g_roiT[M_TOT * 8 * ROI_PER];   // [m][chunk][row16][x18][ci16+2]
__device__ __align__(16) float g_h1  [M_TOT * 64 * 16 * 16];  // padded conv_c1 output
__device__ float g_gap2[M_TOT * 2 * C_IN];
__device__ float g_cpart[M_TOT * 8 * 196];
__device__ float g_ss  [M_TOT * 2];

__device__ __forceinline__ void unpack2(ull v, float& lo, float& hi) {
    asm("mov.b64 {%0, %1}, %2;" : "=f"(lo), "=f"(hi) : "l"(v));
}
__device__ __forceinline__ void ffma2(ull& d, ull a, ull b) {
    asm("fma.rn.f32x2 %0, %1, %2, %3;" : "=l"(d) : "l"(a), "l"(b), "l"(d));
}

// ---------------------------------------------------------------------------
// K1: fused weight transpose + ROI align. grid 1136: [0,624) wt, [624,1136) roi.
// ---------------------------------------------------------------------------
__global__ void k_prep(const float* __restrict__ w_s, const float* __restrict__ w_c1,
                       const float* __restrict__ fmap, const float* __restrict__ boxes)
{
    if (blockIdx.x < 624) {
        int id  = blockIdx.x;             // lab*48 + unit*8 + chunk
        int lab = id / 48, rem = id % 48;
        int unit = rem >> 3, chunk = rem & 7;
        const float* wb = (unit < 4)
            ? w_s  + ((size_t)lab*128 + unit*32)     * 1152
            : w_c1 + ((size_t)lab*64  + (unit-4)*32) * 1152;
        float* dst = g_wT + ((size_t)(lab*6 + unit)*8 + chunk) * WT2;
        for (int d = threadIdx.x; d < WT2; d += 256) {
            int k = d / 512, r2 = d % 512;
            int cg = r2 / 128, r3 = r2 % 128;
            int cp = r3 / 16, oe = r3 % 16;
            int o = oe >> 1, e = oe & 1;
            dst[d] = wb[(size_t)(cg*8 + o)*1152 + chunk*144 + (2*cp + e)*9 + k];
        }
        return;
    }

    int bi = blockIdx.x - 624;            // m*8 + seg
    int m = bi >> 3, seg = bi & 7;
    int b = m >> 4;
    __shared__ int   y0s[14], x0s[14];
    __shared__ float wys[14], wxs[14];

    float b0 = boxes[m*4+0], b1 = boxes[m*4+1], b2 = boxes[m*4+2], b3 = boxes[m*4+3];
    float y1 = 0.6f*b0, x1 = 0.6f*b1;
    float y2 = y1 + 0.1f + 0.3f*b2;
    float x2 = x1 + 0.1f + 0.3f*b3;

    int tid = threadIdx.x;
    if (tid < 14) {
        float t  = (tid + 0.5f) / 14.0f;
        float ys = (y1 + (y2 - y1) * t) * (float)(HF - 1);
        int y0 = (int)floorf(ys);
        if (y0 < 0) y0 = 0; if (y0 > HF-2) y0 = HF-2;
        y0s[tid] = y0;
        wys[tid] = fminf(fmaxf(ys - (float)y0, 0.f), 1.f);
    } else if (tid >= 32 && tid < 46) {
        int j = tid - 32;
        float t  = (j + 0.5f) / 14.0f;
        float xs = (x1 + (x2 - x1) * t) * (float)(WF - 1);
        int x0 = (int)floorf(xs);
        if (x0 < 0) x0 = 0; if (x0 > WF-2) x0 = WF-2;
        x0s[j] = x0;
        wxs[j] = fminf(fmaxf(xs - (float)x0, 0.f), 1.f);
    }
    __syncthreads();

    int base = seg * 16 * 196;
    for (int rel = tid; rel < 16 * 196; rel += 256) {
        int flat = base + rel;
        int c = flat / 196, r = flat % 196;
        int i = r / 14, j = r % 14;
        int y0 = y0s[i], x0 = x0s[j];
        float wy = wys[i], wx = wxs[j];
        const float* f = fmap + (((size_t)(b*C_IN + c) * HF + y0) * WF + x0);
        float v00 = f[0], v01 = f[1], v10 = f[WF], v11 = f[WF+1];
        float v = (1.f-wy)*((1.f-wx)*v00 + wx*v01) + wy*((1.f-wx)*v10 + wx*v11);
        g_roiT[((size_t)m*8 + (c>>4))*ROI_PER + (i+1)*324 + (j+1)*18 + (c&15)] = v;
    }
}

// ---------------------------------------------------------------------------
// K2: fused conv_s (+ReLU+GAP) and conv_c1 (+ReLU). FFMA2 over ci-pairs.
// Warp = co-group -> weight loads are LDS.128 broadcasts (crossbar-cheap).
// grid (12, 64): u = co_unit*2 + pos_half. 128 threads, lanes 0..27 active.
// ---------------------------------------------------------------------------
__global__ void __launch_bounds__(128, 4) k_conv(
    const float* __restrict__ b_s_all, const float* __restrict__ b_c1_all,
    const int* __restrict__ labels)
{
    int u  = blockIdx.x;
    int m  = blockIdx.y;
    int lab = labels[m];
    int co_unit = u >> 1;
    int ph      = u & 1;
    bool is_s = (co_unit < 4);
    int co0 = is_s ? co_unit*32 : (co_unit-4)*32;
    const float* bg = is_s ? (b_s_all + lab*C_IN + co0) : (b_c1_all + lab*64 + co0);

    __shared__ __align__(16) float w_sh [WT2];      // [k][cg][cp][o2]
    __shared__ __align__(16) float in_sh[9*18*18];  // [(row*18+x)][ci18]
    __shared__ float red[32*28];

    int tid  = threadIdx.x;
    int cg   = tid >> 5;                 // warp id = co group
    int lane = tid & 31;
    int row  = lane >> 2;                // 0..6 (lane<28)
    int x0q  = (lane & 3) * 4;
    bool act = lane < 28;

    ull acc[8][4];
    #pragma unroll
    for (int o = 0; o < 8; ++o)
        #pragma unroll
        for (int p = 0; p < 4; ++p) acc[o][p] = 0ull;

    const float* wsrc = g_wT + ((size_t)(lab*6 + co_unit)*8) * WT2;
    const float* isrc = g_roiT + ((size_t)m*8) * ROI_PER + 2268*ph;  // 7*324*ph

    for (int chunk = 0; chunk < 8; ++chunk) {
        __syncthreads();
        const float4* ws = (const float4*)(wsrc + chunk*WT2);
        #pragma unroll
        for (int t = 0; t < 9; ++t)
            ((float4*)w_sh)[tid + t*128] = ws[tid + t*128];   // 1152 float4
        const float4* is = (const float4*)(isrc + chunk*ROI_PER);
        #pragma unroll
        for (int t = 0; t < 6; ++t) {
            int idx = tid + t*128;
            if (idx < 729) ((float4*)in_sh)[idx] = is[idx];
        }
        __syncthreads();

        if (act) {
            #pragma unroll 1
            for (int cp = 0; cp < 8; ++cp) {
                #pragma unroll
                for (int k = 0; k < 9; ++k) {
                    const int kr = k / 3, kc = k % 3;
                    const float* ibase = &in_sh[((row + kr)*18 + x0q + kc)*18 + cp*2];
                    ull ip[4];
                    #pragma unroll
                    for (int p = 0; p < 4; ++p)
                        ip[p] = *(const ull*)&ibase[p*18];
                    const ulonglong2* wq =
                        (const ulonglong2*)&w_sh[((k*4 + cg)*8 + cp)*16];
                    #pragma unroll
                    for (int h = 0; h < 4; ++h) {
                        ulonglong2 wpair = wq[h];
                        #pragma unroll
                        for (int p = 0; p < 4; ++p)
                            ffma2(acc[2*h][p], wpair.x, ip[p]);
                        #pragma unroll
                        for (int p = 0; p < 4; ++p)
                            ffma2(acc[2*h+1][p], wpair.y, ip[p]);
                    }
                }
            }
        }
    }
    __syncthreads();

    if (is_s) {
        if (act) {
            #pragma unroll
            for (int o = 0; o < 8; ++o) {
                float bv = bg[cg*8 + o];
                float s = 0.f;
                #pragma unroll
                for (int p = 0; p < 4; ++p) {
                    float lo, hi; unpack2(acc[o][p], lo, hi);
                    if (x0q + p < 14) s += fmaxf(lo + hi + bv, 0.f);
                }
                red[(cg*8 + o)*28 + row*4 + (lane & 3)] = s;
            }
        }
        __syncthreads();
        if (tid < 32) {
            float s = 0.f;
            #pragma unroll
            for (int i = 0; i < 28; ++i) s += red[tid*28 + i];
            g_gap2[(m*2 + ph)*C_IN + co0 + tid] = s;
        }
    } else if (act) {
        int gi = 7*ph + row;
        #pragma unroll
        for (int o = 0; o < 8; ++o) {
            float bv = bg[cg*8 + o];
            int co = co0 + cg*8 + o;
            #pragma unroll
            for (int p = 0; p < 4; ++p) {
                int x = x0q + p;
                if (x < 14) {
                    float lo, hi; unpack2(acc[o][p], lo, hi);
                    g_h1[((m*64 + co)*16 + gi + 1)*16 + (x + 1)] =
                        fmaxf(lo + hi + bv, 0.f);
                }
            }
        }
    }
}

// ---------------------------------------------------------------------------
// K3: conv_c2 partials (by<8) + FC head (by==8). grid (64,9), 256 threads.
// ---------------------------------------------------------------------------
__global__ void k_conv2fc(const float* __restrict__ w2_all,
                          const float* __restrict__ w_fc, const float* __restrict__ b_fc,
                          const int* __restrict__ labels, float* __restrict__ out)
{
    int m = blockIdx.x;
    int s = blockIdx.y;
    int lab = labels[m];
    int tid = threadIdx.x;

    if (s == 8) {                        // FC: one warp
        if (tid >= 32) return;
        int lane = tid;
        float4 ga = *(const float4*)&g_gap2[m*256 + lane*4];
        float4 gb = *(const float4*)&g_gap2[m*256 + 128 + lane*4];
        float4 w0 = *(const float4*)&w_fc[(size_t)(lab*2    )*128 + lane*4];
        float4 w1 = *(const float4*)&w_fc[(size_t)(lab*2 + 1)*128 + lane*4];
        float g0 = (ga.x + gb.x) * (1.0f/196.0f);
        float g1 = (ga.y + gb.y) * (1.0f/196.0f);
        float g2 = (ga.z + gb.z) * (1.0f/196.0f);
        float g3 = (ga.w + gb.w) * (1.0f/196.0f);
        float s0 = g0*w0.x + g1*w0.y + g2*w0.z + g3*w0.w;
        float s1 = g0*w1.x + g1*w1.y + g2*w1.z + g3*w1.w;
        #pragma unroll
        for (int d = 16; d > 0; d >>= 1) {
            s0 += __shfl_xor_sync(0xffffffffu, s0, d);
            s1 += __shfl_xor_sync(0xffffffffu, s1, d);
        }
        if (lane == 0) {
            s0 += b_fc[lab*2 + 0];
            s1 += b_fc[lab*2 + 1];
            g_ss[m*2 + 0] = s0;
            g_ss[m*2 + 1] = s1;
            out[(size_t)2*SZ_IMG + m]      = s0;
            out[(size_t)2*SZ_IMG + 64 + m] = s1;
        }
        return;
    }

    __shared__ float h_sh[8*16*17];
    __shared__ float w2[72];

    for (int t = tid; t < 512; t += 256) {
        int ci = t / 64, rem4 = (t % 64) * 4;
        float4 v = *(const float4*)&g_h1[(size_t)(m*64 + s*8 + ci)*256 + rem4];
        int r = rem4 >> 4, x0 = rem4 & 15;
        #pragma unroll
        for (int q = 0; q < 4; ++q)
            h_sh[ci*272 + r*17 + x0 + q] = ((const float*)&v)[q];
    }
    if (tid < 72)
        w2[tid] = w2_all[(size_t)lab*576 + s*72 + tid];
    __syncthreads();

    if (tid < 196) {
        int i = tid / 14, j = tid % 14;
        float acc = 0.f;
        #pragma unroll
        for (int ci = 0; ci < 8; ++ci) {
            const float* hh = &h_sh[ci*272 + i*17 + j];
            const float* ww = &w2[ci*9];
            #pragma unroll
            for (int k = 0; k < 9; ++k)
                acc = fmaf(ww[k], hh[(k/3)*17 + (k%3)], acc);
        }
        g_cpart[(m*8 + s)*196 + tid] = acc;
    }
}

// ---------------------------------------------------------------------------
// K4: bilinear upsample + bias + scale/shift. grid (240,64), 320 thr, 2 rows.
// ---------------------------------------------------------------------------
__global__ void k_resize(float* __restrict__ out,
                         const float* __restrict__ b2_all, const int* __restrict__ labels)
{
    int m = blockIdx.y;
    __shared__ float r0[2][14], r1[2][14];
    __shared__ float s_sc, s_sh, s_b2;
    int tid  = threadIdx.x;
    int half = tid / 160;
    int xq   = tid % 160;
    int Y = blockIdx.x*2 + half;

    float iy = (Y + 0.5f) * (14.0f/480.0f) - 0.5f;
    iy = fminf(fmaxf(iy, 0.f), 13.f);
    int y0 = (int)iy; if (y0 > 12) y0 = 12;
    float fy = iy - (float)y0;

    if (xq < 14) {
        float a = 0.f, b = 0.f;
        #pragma unroll
        for (int s = 0; s < 8; ++s) {
            a += g_cpart[(m*8 + s)*196 + y0*14 + xq];
            b += g_cpart[(m*8 + s)*196 + (y0+1)*14 + xq];
        }
        r0[half][xq] = a; r1[half][xq] = b;
    }
    if (tid == 14) s_sc = g_ss[m*2 + 0];
    if (tid == 15) s_sh = g_ss[m*2 + 1];
    if (tid == 16) s_b2 = b2_all[labels[m]];
    __syncthreads();

    float scale = s_sc, shift = s_sh, b2v = s_b2;
    size_t base = (size_t)m * H_OUT * W_OUT + (size_t)Y * W_OUT;

    float can4[4], dep4[4];
    #pragma unroll
    for (int uu = 0; uu < 4; ++uu) {
        int X = xq*4 + uu;
        float ix = (X + 0.5f) * (14.0f/640.0f) - 0.5f;
        ix = fminf(fmaxf(ix, 0.f), 13.f);
        int x0 = (int)ix; if (x0 > 12) x0 = 12;
        float fx = ix - (float)x0;
        float top = (1.f-fx)*r0[half][x0] + fx*r0[half][x0+1];
        float bot = (1.f-fx)*r1[half][x0] + fx*r1[half][x0+1];
        float can = (1.f-fy)*top + fy*bot + b2v;
        can4[uu] = can;
        dep4[uu] = fmaxf(can*scale + shift, 0.001f);
    }
    ((float4*)(out + base))[xq] = make_float4(dep4[0], dep4[1], dep4[2], dep4[3]);
    ((float4*)(out + SZ_IMG + base))[xq] = make_float4(can4[0], can4[1], can4[2], can4[3]);
}

// ---------------------------------------------------------------------------
extern "C" void kernel_launch(void* const* d_in, const int* in_sizes, int n_in,
                              void* d_out, int out_size)
{
    (void)in_sizes; (void)out_size;
    const float* fmap      = (const float*)d_in[2];
    const float* boxes     = (const float*)d_in[n_in-10];
    const int*   labels    = (const int*)  d_in[n_in-9];
    const float* w_conv_s  = (const float*)d_in[n_in-8];
    const float* b_conv_s  = (const float*)d_in[n_in-7];
    const float* w_fc      = (const float*)d_in[n_in-6];
    const float* b_fc      = (const float*)d_in[n_in-5];
    const float* w_conv_c1 = (const float*)d_in[n_in-4];
    const float* b_conv_c1 = (const float*)d_in[n_in-3];
    const float* w_conv_c2 = (const float*)d_in[n_in-2];
    const float* b_conv_c2 = (const float*)d_in[n_in-1];
    float* out = (float*)d_out;

    k_prep   <<<1136, 256>>>(w_conv_s, w_conv_c1, fmap, boxes);
    k_conv   <<<dim3(12, 64), 128>>>(b_conv_s, b_conv_c1, labels);
    k_conv2fc<<<dim3(64, 9), 256>>>(w_conv_c2, w_fc, b_fc, labels, out);
    k_resize <<<dim3(240, 64), 320>>>(out, b_conv_c2, labels);
}